// round 13
// baseline (speedup 1.0000x reference)
#include <cuda_runtime.h>
#include <cuda_bf16.h>
#include <cstdint>

typedef unsigned long long ull;
typedef uint32_t u32;

#define ROWS_IMG 12996          // 114*114 padded pixels per image
#define GUARD    128
#define TAIL     256
#define TOT_ROWS (GUARD + 32 * ROWS_IMG + TAIL)

// scratch: [row][192 s8] : digit0(64 ci) | digit1(64) | digit2(64)
__device__ __align__(16) signed char g_scratch[(size_t)TOT_ROWS * 192];
__device__ __align__(16) signed char g_wsign[9 * 64 * 64];   // [tap][co][ci] in {-1,0,1}
__device__ float g_wscale[64];                               // pow2 per-co scale

// ---------------- helpers ----------------
__device__ __forceinline__ u32 smem_u32(const void* p) {
    u32 a;
    asm("{ .reg .u64 t; cvta.to.shared.u64 t, %1; cvt.u32.u64 %0, t; }" : "=r"(a) : "l"(p));
    return a;
}
__device__ __forceinline__ void cp16(u32 dst, const void* src) {
    asm volatile("cp.async.cg.shared.global [%0], [%1], 16;" :: "r"(dst), "l"(src));
}
#define CP_COMMIT() asm volatile("cp.async.commit_group;" ::: "memory")

__device__ __forceinline__ void ldm4(u32* r, u32 addr) {
    asm volatile("ldmatrix.sync.aligned.m8n8.x4.shared.b16 {%0,%1,%2,%3}, [%4];"
                 : "=r"(r[0]), "=r"(r[1]), "=r"(r[2]), "=r"(r[3]) : "r"(addr));
}
__device__ __forceinline__ void imma16832(int* c, const u32* a, u32 b0, u32 b1) {
    asm volatile(
        "mma.sync.aligned.m16n8k32.row.col.s32.s8.s8.s32 "
        "{%0,%1,%2,%3}, {%4,%5,%6,%7}, {%8,%9}, {%0,%1,%2,%3};"
        : "+r"(c[0]), "+r"(c[1]), "+r"(c[2]), "+r"(c[3])
        : "r"(a[0]), "r"(a[1]), "r"(a[2]), "r"(a[3]), "r"(b0), "r"(b1));
}

// ---------------------------------------------------------------------------
// convert32: 128-thread block converts 32 pixels (q0..q0+31) of image n.
// x = d0*2^-4 + d1*2^-11 + d2*2^-18 + eps, |eps| <= 2^-19 (exact digits)
// sm points at a [64][33] float staging area.
// ---------------------------------------------------------------------------
__device__ __forceinline__ void convert32(const float* __restrict__ x,
                                          float (*sm)[33], int n, int q0) {
    const int t = threadIdx.x, lane = t & 31, wq = t >> 5;
    #pragma unroll
    for (int r = 0; r < 16; ++r) {
        const int ci = wq * 16 + r;
        sm[ci][lane] = x[((size_t)n * 64 + ci) * 12544 + q0 + lane];
    }
    __syncthreads();
    const int pix = t >> 2, g = t & 3;
    const int q = q0 + pix;
    const int rr = q / 112, cc = q - rr * 112;
    const size_t row = GUARD + (size_t)n * ROWS_IMG + (size_t)(rr + 1) * 114 + cc;
    signed char* dst = g_scratch + row * 192 + g * 16;
    #pragma unroll
    for (int h = 0; h < 2; ++h) {
        union { signed char b[8]; ull u; } p0, p1, p2;
        #pragma unroll
        for (int i = 0; i < 8; ++i) {
            const float f = sm[g * 16 + h * 8 + i][pix];
            float a0 = fminf(127.f, fmaxf(-128.f, rintf(f * 16.f)));
            const float r1 = fmaf(a0, -0.0625f, f);
            float a1 = fminf(127.f, fmaxf(-127.f, rintf(r1 * 2048.f)));
            const float r2 = fmaf(a1, -4.8828125e-4f, r1);
            float a2 = fminf(127.f, fmaxf(-127.f, rintf(r2 * 262144.f)));
            p0.b[i] = (signed char)(int)a0;
            p1.b[i] = (signed char)(int)a1;
            p2.b[i] = (signed char)(int)a2;
        }
        *reinterpret_cast<ull*>(dst + h * 8)       = p0.u;
        *reinterpret_cast<ull*>(dst + 64 + h * 8)  = p1.u;
        *reinterpret_cast<ull*>(dst + 128 + h * 8) = p2.u;
    }
    __syncthreads();
}

// ---------------------------------------------------------------------------
// Head kernel (128 threads):
//   blocks [0, 660)      : convert images 0..9  (66 blocks/img, 192 px each)
//   blocks [660, 693)    : pad/zero scratch borders + guard + tail
//   blocks [693, 757)    : binarize weights -> sign + pow2 scale
// ---------------------------------------------------------------------------
#define CVT_PER_IMG 66
#define HEAD_CVT (CVT_PER_IMG * 10)      // 660
#define PAD_BLKS 33
#define HEAD_BLKS (HEAD_CVT + PAD_BLKS + 64)

__global__ void __launch_bounds__(128)
prepass_head(const float* __restrict__ x, const float* __restrict__ w) {
    const int bid = blockIdx.x;
    const int t = threadIdx.x;

    if (bid < HEAD_CVT) {
        __shared__ float sm[64][33];
        const int img = bid / CVT_PER_IMG;
        const int base = (bid % CVT_PER_IMG) * 6;
        #pragma unroll 1
        for (int k = 0; k < 6; ++k) {
            const int qb = base + k;
            if (qb < 392) convert32(x, sm, img, qb * 32);
        }
        return;
    }

    if (bid < HEAD_CVT + PAD_BLKS) {
        // ---------------- pad / zero (all 32 images) ----------------
        const int pb = bid - HEAD_CVT;
        uint4* base = reinterpret_cast<uint4*>(g_scratch);   // 12 uint4 per row
        const uint4 z = make_uint4(0, 0, 0, 0);
        if (pb == 32) {
            for (int i = t; i < GUARD * 12; i += 128) base[i] = z;
            uint4* tail = base + ((size_t)GUARD + 32 * (size_t)ROWS_IMG) * 12;
            for (int i = t; i < TAIL * 12; i += 128) tail[i] = z;
            return;
        }
        const size_t imgrow0 = GUARD + (size_t)pb * ROWS_IMG;
        for (int i = t; i < 228 * 12; i += 128) {
            const int r = i / 12, c = i % 12;
            const size_t row = imgrow0 + (r < 114 ? r : (12882 - 114 + r));
            base[row * 12 + c] = z;
        }
        for (int i = t; i < 112 * 2 * 12; i += 128) {
            const int rp  = 1 + i / 24;
            const int col = 112 + ((i / 12) & 1);
            const int c   = i % 12;
            base[(imgrow0 + (size_t)rp * 114 + col) * 12 + c] = z;
        }
        return;
    }

    // ---------------- binarize (128 threads, 576 elements) ----------------
    {
        __shared__ float rs[4], rsq[4], rab[4];
        __shared__ float s_mean, s_scale;
        const int co = bid - (HEAD_CVT + PAD_BLKS);
        const int lane = t & 31, wq = t >> 5;
        const bool has5 = (t < 64);
        float v[5];
        #pragma unroll
        for (int k = 0; k < 4; ++k) v[k] = w[co * 576 + t + 128 * k];
        v[4] = has5 ? w[co * 576 + t + 512] : 0.f;

        float s = v[0] + v[1] + v[2] + v[3] + v[4];
        #pragma unroll
        for (int o = 16; o > 0; o >>= 1) s += __shfl_down_sync(0xffffffffu, s, o);
        if (lane == 0) rs[wq] = s;
        __syncthreads();
        if (t == 0) s_mean = (rs[0] + rs[1] + rs[2] + rs[3]) * (1.0f / 576.0f);
        __syncthreads();
        const float mean = s_mean;
        float d[5];
        #pragma unroll
        for (int k = 0; k < 4; ++k) d[k] = v[k] - mean;
        d[4] = has5 ? (v[4] - mean) : 0.f;
        float sq = 0.f, ab = 0.f;
        #pragma unroll
        for (int k = 0; k < 5; ++k) { sq += d[k] * d[k]; ab += fabsf(d[k]); }
        #pragma unroll
        for (int o = 16; o > 0; o >>= 1) {
            sq += __shfl_down_sync(0xffffffffu, sq, o);
            ab += __shfl_down_sync(0xffffffffu, ab, o);
        }
        if (lane == 0) { rsq[wq] = sq; rab[wq] = ab; }
        __syncthreads();
        if (t == 0) {
            const float t2 = rsq[0] + rsq[1] + rsq[2] + rsq[3];
            const float t3 = rab[0] + rab[1] + rab[2] + rab[3];
            const float stdv = sqrtf(t2 / 575.0f);
            const float mean_abs = t3 / (576.0f * stdv);
            s_scale = exp2f(rintf(log2f(mean_abs)));
        }
        __syncthreads();
        #pragma unroll
        for (int k = 0; k < 4; ++k) {
            const int e = t + 128 * k;
            const signed char sg = (d[k] > 0.f) ? 1 : ((d[k] < 0.f) ? -1 : 0);
            g_wsign[((e % 9) * 64 + co) * 64 + (e / 9)] = sg;
        }
        if (has5) {
            const int e = t + 512;
            const signed char sg = (d[4] > 0.f) ? 1 : ((d[4] < 0.f) ? -1 : 0);
            g_wsign[((e % 9) * 64 + co) * 64 + (e / 9)] = sg;
        }
        if (t == 0) g_wscale[co] = s_scale;
    }
}

// ---------------------------------------------------------------------------
// Fused kernel: conv blocks + interleaved convert blocks (single launch).
// Block index mapping: odd bids with (bid>>1) < cvtBlocks are convert blocks;
// the rest are conv blocks in order. Conv: 128 threads, tile M=128 x N=64,
// 2 CTAs/SM, digit-outer s32 shift-merge, scaled LUT (identical to R11).
// ---------------------------------------------------------------------------
#define AROWS   358                       // 128 + 2*114 + 2
#define APITCH  208
#define A_OFF   0
#define B_OFF   74464                     // 358*208
#define BPITCH  592                       // conflict-free
#define LUT_OFF (B_OFF + 64 * BPITCH)     // 112352
#define SMEM_TOTAL (LUT_OFF + 1792 + 32)  // 114176

__global__ void __launch_bounds__(128, 2)
fused_kernel(const float* __restrict__ x, const float* __restrict__ lut,
             float* __restrict__ out, int n0, int c0, int cvtBlocks) {
    extern __shared__ __align__(1024) char smem[];
    const int bid = blockIdx.x;

    // ---------------- convert path ----------------
    if (((bid & 1) == 1) && ((bid >> 1) < cvtBlocks)) {
        float (*sm)[33] = reinterpret_cast<float (*)[33]>(smem);
        const int cid = bid >> 1;
        const int img = c0 + cid / CVT_PER_IMG;
        const int base = (cid % CVT_PER_IMG) * 6;
        #pragma unroll 1
        for (int k = 0; k < 6; ++k) {
            const int qb = base + k;
            if (qb < 392) convert32(x, sm, img, qb * 32);
        }
        return;
    }

    // ---------------- conv path ----------------
    const int cmin = ((bid >> 1) < cvtBlocks) ? (bid >> 1) : cvtBlocks;
    const int conv_id = bid - cmin;
    const int tile = conv_id % 100;
    const int n = n0 + conv_id / 100;

    const u32 sb = smem_u32(smem);
    const int tid = threadIdx.x, warp = tid >> 5, lane = tid & 31;
    const int wm = warp >> 1;            // 0/1 : 64-px half
    const int wn = warp & 1;             // 0/1 : 32-co half
    const int s0 = 114 + tile * 128;
    const size_t imgrow0 = GUARD + (size_t)n * ROWS_IMG;
    const long g0 = (long)s0 - 115;

    const char* abase = reinterpret_cast<const char*>(g_scratch) +
                        ((size_t)imgrow0 + g0) * 192;

    // ---- group 1: B ([co][tap*64] repack) + A digit-0 ----
    {
        const char* wsrc = reinterpret_cast<const char*>(g_wsign);
        for (int i = tid; i < 64 * 9 * 4; i += 128) {
            const int tap9 = (i >> 2) % 9, co9 = i / 36, c16 = i & 3;
            cp16(sb + B_OFF + co9 * BPITCH + tap9 * 64 + c16 * 16,
                 wsrc + (size_t)(tap9 * 64 + co9) * 64 + c16 * 16);
        }
        for (int i = tid; i < AROWS * 4; i += 128) {
            const int r = i >> 2, c = i & 3;
            cp16(sb + A_OFF + r * APITCH + c * 16, abase + (size_t)r * 192 + c * 16);
        }
    }
    // scaled LUT: compare raw (float)acc against t * 2^18 / ws  (exact pow2 scaling)
    for (int i = tid; i < 448; i += 128) {
        const int co = i / 7;
        reinterpret_cast<float*>(smem + LUT_OFF)[i] =
            lut[i] * (262144.0f / g_wscale[co]);
    }
    CP_COMMIT();
    // ---- group 2: A digit-1 ----
    for (int i = tid; i < AROWS * 4; i += 128) {
        const int r = i >> 2, c = (i & 3) + 4;
        cp16(sb + A_OFF + r * APITCH + c * 16, abase + (size_t)r * 192 + c * 16);
    }
    CP_COMMIT();
    // ---- group 3: A digit-2 ----
    for (int i = tid; i < AROWS * 4; i += 128) {
        const int r = i >> 2, c = (i & 3) + 8;
        cp16(sb + A_OFF + r * APITCH + c * 16, abase + (size_t)r * 192 + c * 16);
    }
    CP_COMMIT();

    // ---- mainloop: digit-outer, one s32 acc set, shift-merge ----
    const int laneR = lane & 15;
    const int blk   = lane >> 4;
    const u32 abase_t = sb + A_OFF + (wm * 64 + laneR) * APITCH + blk * 16;
    const u32 bbase_t = sb + B_OFF + (wn * 32 + laneR) * BPITCH + blk * 16;

    int sacc[4][4][4];
    #pragma unroll
    for (int mt = 0; mt < 4; ++mt)
        #pragma unroll
        for (int nt = 0; nt < 4; ++nt)
            #pragma unroll
            for (int i = 0; i < 4; ++i) sacc[mt][nt][i] = 0;

    #pragma unroll
    for (int d = 0; d < 3; ++d) {
        if (d == 0)      asm volatile("cp.async.wait_group 2;" ::: "memory");
        else if (d == 1) asm volatile("cp.async.wait_group 1;" ::: "memory");
        else             asm volatile("cp.async.wait_group 0;" ::: "memory");
        __syncthreads();

        #pragma unroll
        for (int s = 0; s < 18; ++s) {
            const int tap = s >> 1, kc = s & 1;
            const int kh = tap / 3, kw = tap - kh * 3;
            u32 af[16], bf[8];
            const u32 ka = abase_t + (kh * 114 + kw) * APITCH + d * 64 + kc * 32;
            ldm4(&af[0],  ka);
            ldm4(&af[4],  ka + 16 * APITCH);
            ldm4(&af[8],  ka + 32 * APITCH);
            ldm4(&af[12], ka + 48 * APITCH);
            const u32 bk = bbase_t + tap * 64 + kc * 32;
            ldm4(&bf[0], bk);
            ldm4(&bf[4], bk + 16 * BPITCH);
            #pragma unroll
            for (int mt = 0; mt < 4; ++mt) {
                imma16832(sacc[mt][0], &af[mt * 4], bf[0], bf[2]);
                imma16832(sacc[mt][1], &af[mt * 4], bf[1], bf[3]);
                imma16832(sacc[mt][2], &af[mt * 4], bf[4], bf[6]);
                imma16832(sacc[mt][3], &af[mt * 4], bf[5], bf[7]);
            }
        }

        if (d < 2) {   // exact merge: next digit is 2^-7 smaller
            #pragma unroll
            for (int mt = 0; mt < 4; ++mt)
                #pragma unroll
                for (int nt = 0; nt < 4; ++nt)
                    #pragma unroll
                    for (int i = 0; i < 4; ++i) sacc[mt][nt][i] <<= 7;
        }
    }

    // ---- epilogue: raw (float)acc -> smem [px][65]; max-index bucketize ----
    __syncthreads();
    float* sum = reinterpret_cast<float*>(smem);
    #pragma unroll
    for (int mt = 0; mt < 4; ++mt)
        #pragma unroll
        for (int nt = 0; nt < 4; ++nt)
            #pragma unroll
            for (int i = 0; i < 4; ++i) {
                const int row = wm * 64 + mt * 16 + (lane >> 2) + ((i >> 1) << 3);
                const int col = wn * 32 + nt * 8 + ((lane & 3) << 1) + (i & 1);
                sum[row * 65 + col] = (float)sacc[mt][nt][i];
            }
    __syncthreads();

    const int j = tid;                   // pixel 0..127
    const int s = s0 + j;
    const int rimg = s / 114 - 1;
    const int c = s - (rimg + 1) * 114;
    if (c < 112 && rimg < 112) {
        const int q = rimg * 112 + c;
        float* op = out + (size_t)n * 64 * 12544 + q;
        const float* sl = reinterpret_cast<const float*>(smem + LUT_OFF);
        #pragma unroll 4
        for (int co = 0; co < 64; ++co) {
            const float v = sum[j * 65 + co];
            const float* tt = sl + co * 7;
            float r = 0.f;
            if (v >  tt[0]) r = 1.f;
            if (v >= tt[1]) r = 2.f;
            if (v >  tt[2]) r = 3.f;
            if (v >= tt[3]) r = 4.f;
            if (v >  tt[4]) r = 5.f;
            if (v >= tt[5]) r = 6.f;
            if (v >  tt[6]) r = 7.f;
            op[(size_t)co * 12544] = r;
        }
    }
}

// ---------------------------------------------------------------------------
extern "C" void kernel_launch(void* const* d_in, const int* in_sizes, int n_in,
                              void* d_out, int out_size) {
    (void)in_sizes; (void)n_in; (void)out_size;
    const float* x   = (const float*)d_in[0];
    const float* w   = (const float*)d_in[1];
    const float* lut = (const float*)d_in[2];
    float* out = (float*)d_out;

    cudaFuncSetAttribute(fused_kernel,
                         cudaFuncAttributeMaxDynamicSharedMemorySize, SMEM_TOTAL);

    const int CVT11 = CVT_PER_IMG * 11;   // 726 convert blocks per fused launch

    // head: binarize + pad + convert images 0..9
    prepass_head<<<HEAD_BLKS, 128>>>(x, w);
    // fused 1: conv images 0..9 (1000 blocks) + convert images 10..20
    fused_kernel<<<1000 + CVT11, 128, SMEM_TOTAL>>>(x, lut, out, 0, 10, CVT11);
    // fused 2: conv images 10..20 (1100 blocks) + convert images 21..31
    fused_kernel<<<1100 + CVT11, 128, SMEM_TOTAL>>>(x, lut, out, 10, 21, CVT11);
    // fused 3: conv images 21..31 (1100 blocks), no converts
    fused_kernel<<<1100, 128, SMEM_TOTAL>>>(x, lut, out, 21, 0, 0);
}

// round 14
// speedup vs baseline: 1.3216x; 1.3216x over previous
#include <cuda_runtime.h>
#include <cuda_bf16.h>
#include <cstdint>

typedef unsigned long long ull;
typedef uint32_t u32;

#define ROWS_IMG 12996          // 114*114 padded pixels per image
#define GUARD    128
#define TAIL     256
#define TOT_ROWS (GUARD + 32 * ROWS_IMG + TAIL)

// scratch: [row][192 s8] : digit0(64 ci) | digit1(64) | digit2(64)
__device__ __align__(16) signed char g_scratch[(size_t)TOT_ROWS * 192];
__device__ __align__(16) signed char g_wsign[9 * 64 * 64];   // [tap][co][ci] in {-1,0,1}
__device__ float g_wscale[64];                               // pow2 per-co scale

// ---------------- helpers ----------------
__device__ __forceinline__ u32 smem_u32(const void* p) {
    u32 a;
    asm("{ .reg .u64 t; cvta.to.shared.u64 t, %1; cvt.u32.u64 %0, t; }" : "=r"(a) : "l"(p));
    return a;
}
__device__ __forceinline__ void cp16(u32 dst, const void* src) {
    asm volatile("cp.async.cg.shared.global [%0], [%1], 16;" :: "r"(dst), "l"(src));
}
#define CP_COMMIT() asm volatile("cp.async.commit_group;" ::: "memory")

__device__ __forceinline__ void ldm4(u32* r, u32 addr) {
    asm volatile("ldmatrix.sync.aligned.m8n8.x4.shared.b16 {%0,%1,%2,%3}, [%4];"
                 : "=r"(r[0]), "=r"(r[1]), "=r"(r[2]), "=r"(r[3]) : "r"(addr));
}
__device__ __forceinline__ void imma16832(int* c, const u32* a, u32 b0, u32 b1) {
    asm volatile(
        "mma.sync.aligned.m16n8k32.row.col.s32.s8.s8.s32 "
        "{%0,%1,%2,%3}, {%4,%5,%6,%7}, {%8,%9}, {%0,%1,%2,%3};"
        : "+r"(c[0]), "+r"(c[1]), "+r"(c[2]), "+r"(c[3])
        : "r"(a[0]), "r"(a[1]), "r"(a[2]), "r"(a[3]), "r"(b0), "r"(b1));
}

// ---------------------------------------------------------------------------
// Merged pre-pass kernel, 256 threads/block (identical to the R11 version):
//   blocks [0, 12544)        : convert  (x fp32 -> 3x s8 digit scratch rows)
//   blocks [12544, 12577)    : pad/zero scratch borders + guard + tail
//   blocks [12577, 12641)    : binarize weights -> sign + pow2 scale
// ---------------------------------------------------------------------------
#define CONV_BLKS 12544          // 392 per image * 32 images
#define PAD_BLKS  33
#define PRE_BLKS  (CONV_BLKS + PAD_BLKS + 64)

__global__ void __launch_bounds__(256)
prepass_kernel(const float* __restrict__ x, const float* __restrict__ w) {
    const int bid = blockIdx.x;
    const int t = threadIdx.x;

    if (bid < CONV_BLKS) {
        // ---------------- convert ----------------
        __shared__ float sm[64][33];
        const int n = bid / 392;
        const int q0 = (bid - n * 392) * 32;
        const int w8 = t >> 5, l = t & 31;
        #pragma unroll
        for (int r = 0; r < 8; ++r) {
            const int ci = w8 * 8 + r;
            sm[ci][l] = x[((size_t)n * 64 + ci) * 12544 + q0 + l];
        }
        __syncthreads();
        const int pix = t >> 3, g = t & 7;
        const int q = q0 + pix;
        const int r = q / 112, c = q - r * 112;
        const size_t row = GUARD + (size_t)n * ROWS_IMG + (size_t)(r + 1) * 114 + c;
        signed char* dst = g_scratch + row * 192 + g * 8;

        union { signed char b[8]; ull u; } p0, p1, p2;
        #pragma unroll
        for (int i = 0; i < 8; ++i) {
            const float f = sm[g * 8 + i][pix];
            float a0 = fminf(127.f, fmaxf(-128.f, rintf(f * 16.f)));
            const float r1 = fmaf(a0, -0.0625f, f);
            float a1 = fminf(127.f, fmaxf(-127.f, rintf(r1 * 2048.f)));
            const float r2 = fmaf(a1, -4.8828125e-4f, r1);
            float a2 = fminf(127.f, fmaxf(-127.f, rintf(r2 * 262144.f)));
            p0.b[i] = (signed char)(int)a0;
            p1.b[i] = (signed char)(int)a1;
            p2.b[i] = (signed char)(int)a2;
        }
        *reinterpret_cast<ull*>(dst)       = p0.u;
        *reinterpret_cast<ull*>(dst + 64)  = p1.u;
        *reinterpret_cast<ull*>(dst + 128) = p2.u;
        return;
    }

    if (bid < CONV_BLKS + PAD_BLKS) {
        // ---------------- pad / zero ----------------
        const int pb = bid - CONV_BLKS;
        uint4* base = reinterpret_cast<uint4*>(g_scratch);   // 12 uint4 per row
        const uint4 z = make_uint4(0, 0, 0, 0);
        if (pb == 32) {
            for (int i = t; i < GUARD * 12; i += 256) base[i] = z;
            uint4* tail = base + ((size_t)GUARD + 32 * (size_t)ROWS_IMG) * 12;
            for (int i = t; i < TAIL * 12; i += 256) tail[i] = z;
            return;
        }
        const size_t imgrow0 = GUARD + (size_t)pb * ROWS_IMG;
        for (int i = t; i < 228 * 12; i += 256) {
            const int r = i / 12, c = i % 12;
            const size_t row = imgrow0 + (r < 114 ? r : (12882 - 114 + r));
            base[row * 12 + c] = z;
        }
        for (int i = t; i < 112 * 2 * 12; i += 256) {
            const int rp  = 1 + i / 24;
            const int col = 112 + ((i / 12) & 1);
            const int c   = i % 12;
            base[(imgrow0 + (size_t)rp * 114 + col) * 12 + c] = z;
        }
        return;
    }

    // ---------------- binarize (256 threads, 576 elements) ----------------
    {
        __shared__ float rs[8], rsq[8], rab[8];
        __shared__ float s_mean, s_scale;
        const int co = bid - (CONV_BLKS + PAD_BLKS);
        const int lane = t & 31, wid = t >> 5;
        const bool has3 = (t < 64);
        const float v0 = w[co * 576 + t];
        const float v1 = w[co * 576 + t + 256];
        const float v2 = has3 ? w[co * 576 + t + 512] : 0.f;

        float s = v0 + v1 + v2;
        #pragma unroll
        for (int o = 16; o > 0; o >>= 1) s += __shfl_down_sync(0xffffffffu, s, o);
        if (lane == 0) rs[wid] = s;
        __syncthreads();
        if (t == 0) {
            float tt = 0.f;
            for (int i = 0; i < 8; ++i) tt += rs[i];
            s_mean = tt * (1.0f / 576.0f);
        }
        __syncthreads();
        const float mean = s_mean;
        const float d0 = v0 - mean, d1 = v1 - mean;
        const float d2 = has3 ? (v2 - mean) : 0.f;
        float sq = d0 * d0 + d1 * d1 + d2 * d2;
        float ab = fabsf(d0) + fabsf(d1) + fabsf(d2);
        #pragma unroll
        for (int o = 16; o > 0; o >>= 1) {
            sq += __shfl_down_sync(0xffffffffu, sq, o);
            ab += __shfl_down_sync(0xffffffffu, ab, o);
        }
        if (lane == 0) { rsq[wid] = sq; rab[wid] = ab; }
        __syncthreads();
        if (t == 0) {
            float t2 = 0.f, t3 = 0.f;
            for (int i = 0; i < 8; ++i) { t2 += rsq[i]; t3 += rab[i]; }
            const float stdv = sqrtf(t2 / 575.0f);
            const float mean_abs = t3 / (576.0f * stdv);
            s_scale = exp2f(rintf(log2f(mean_abs)));
        }
        __syncthreads();
        {
            const int e0 = t;
            const signed char sg0 = (d0 > 0.f) ? 1 : ((d0 < 0.f) ? -1 : 0);
            g_wsign[((e0 % 9) * 64 + co) * 64 + (e0 / 9)] = sg0;
            const int e1 = t + 256;
            const signed char sg1 = (d1 > 0.f) ? 1 : ((d1 < 0.f) ? -1 : 0);
            g_wsign[((e1 % 9) * 64 + co) * 64 + (e1 / 9)] = sg1;
            if (has3) {
                const int e2 = t + 512;
                const signed char sg2 = (d2 > 0.f) ? 1 : ((d2 < 0.f) ? -1 : 0);
                g_wsign[((e2 % 9) * 64 + co) * 64 + (e2 / 9)] = sg2;
            }
        }
        if (t == 0) g_wscale[co] = s_scale;
    }
}

// ---------------------------------------------------------------------------
// Main kernel: PERSISTENT implicit-GEMM conv, mma.sync m16n8k32 s8 + LUT.
// Grid = 296 CTAs (2/SM), each loops over (tile, image) work items.
// B tile + scaled LUT staged ONCE per CTA. Per item: 3 digit A-stages via
// cp.async groups, digit-outer s32 shift-merge, max-index bucketize.
// ---------------------------------------------------------------------------
#define AROWS   358                       // 128 + 2*114 + 2
#define APITCH  208
#define A_OFF   0
#define B_OFF   74464                     // 358*208
#define BPITCH  592                       // conflict-free
#define LUT_OFF (B_OFF + 64 * BPITCH)     // 112352
#define SMEM_TOTAL (LUT_OFF + 1792 + 32)  // 114176
#define NCTAS   296
#define NWORK   3200

__global__ void __launch_bounds__(128, 2)
conv_mma_kernel(const float* __restrict__ lut, float* __restrict__ out) {
    extern __shared__ __align__(1024) char smem[];
    const u32 sb = smem_u32(smem);
    const int tid = threadIdx.x, warp = tid >> 5, lane = tid & 31;
    const int wm = warp >> 1;            // 0/1 : 64-px half
    const int wn = warp & 1;             // 0/1 : 32-co half

    // ---- one-time staging: B ([co][tap*64] repack) in its own cp group ----
    {
        const char* wsrc = reinterpret_cast<const char*>(g_wsign);
        for (int i = tid; i < 64 * 9 * 4; i += 128) {
            const int tap9 = (i >> 2) % 9, co9 = i / 36, c16 = i & 3;
            cp16(sb + B_OFF + co9 * BPITCH + tap9 * 64 + c16 * 16,
                 wsrc + (size_t)(tap9 * 64 + co9) * 64 + c16 * 16);
        }
    }
    // one-time scaled LUT: compare raw (float)acc against t * 2^18 / ws
    for (int i = tid; i < 448; i += 128) {
        const int co = i / 7;
        reinterpret_cast<float*>(smem + LUT_OFF)[i] =
            lut[i] * (262144.0f / g_wscale[co]);
    }
    CP_COMMIT();                         // group: B

    const int laneR = lane & 15;
    const int blk   = lane >> 4;
    const u32 abase_t0 = sb + A_OFF + (wm * 64 + laneR) * APITCH + blk * 16;
    const u32 bbase_t  = sb + B_OFF + (wn * 32 + laneR) * BPITCH + blk * 16;

    for (int wi = blockIdx.x; wi < NWORK; wi += NCTAS) {
        const int tile = wi % 100;
        const int n = wi / 100;
        const int s0 = 114 + tile * 128;
        const size_t imgrow0 = GUARD + (size_t)n * ROWS_IMG;
        const char* abase = reinterpret_cast<const char*>(g_scratch) +
                            ((size_t)imgrow0 + (long)s0 - 115) * 192;

        // ---- A stages: 3 digit groups ----
        for (int i = tid; i < AROWS * 4; i += 128) {
            const int r = i >> 2, c = i & 3;
            cp16(sb + A_OFF + r * APITCH + c * 16, abase + (size_t)r * 192 + c * 16);
        }
        CP_COMMIT();                     // group: d0
        for (int i = tid; i < AROWS * 4; i += 128) {
            const int r = i >> 2, c = (i & 3) + 4;
            cp16(sb + A_OFF + r * APITCH + c * 16, abase + (size_t)r * 192 + c * 16);
        }
        CP_COMMIT();                     // group: d1
        for (int i = tid; i < AROWS * 4; i += 128) {
            const int r = i >> 2, c = (i & 3) + 8;
            cp16(sb + A_OFF + r * APITCH + c * 16, abase + (size_t)r * 192 + c * 16);
        }
        CP_COMMIT();                     // group: d2

        // ---- mainloop: digit-outer, one s32 acc set, shift-merge ----
        int sacc[4][4][4];
        #pragma unroll
        for (int mt = 0; mt < 4; ++mt)
            #pragma unroll
            for (int nt = 0; nt < 4; ++nt)
                #pragma unroll
                for (int i = 0; i < 4; ++i) sacc[mt][nt][i] = 0;

        #pragma unroll
        for (int d = 0; d < 3; ++d) {
            // pending groups at this point: d0,d1,d2 (B long drained after 1st iter)
            if (d == 0)      asm volatile("cp.async.wait_group 2;" ::: "memory");
            else if (d == 1) asm volatile("cp.async.wait_group 1;" ::: "memory");
            else             asm volatile("cp.async.wait_group 0;" ::: "memory");
            __syncthreads();

            #pragma unroll
            for (int s = 0; s < 18; ++s) {
                const int tap = s >> 1, kc = s & 1;
                const int kh = tap / 3, kw = tap - kh * 3;
                u32 af[16], bf[8];
                const u32 ka = abase_t0 + (kh * 114 + kw) * APITCH + d * 64 + kc * 32;
                ldm4(&af[0],  ka);
                ldm4(&af[4],  ka + 16 * APITCH);
                ldm4(&af[8],  ka + 32 * APITCH);
                ldm4(&af[12], ka + 48 * APITCH);
                const u32 bk = bbase_t + tap * 64 + kc * 32;
                ldm4(&bf[0], bk);
                ldm4(&bf[4], bk + 16 * BPITCH);
                #pragma unroll
                for (int mt = 0; mt < 4; ++mt) {
                    imma16832(sacc[mt][0], &af[mt * 4], bf[0], bf[2]);
                    imma16832(sacc[mt][1], &af[mt * 4], bf[1], bf[3]);
                    imma16832(sacc[mt][2], &af[mt * 4], bf[4], bf[6]);
                    imma16832(sacc[mt][3], &af[mt * 4], bf[5], bf[7]);
                }
            }

            if (d < 2) {   // exact merge: next digit is 2^-7 smaller
                #pragma unroll
                for (int mt = 0; mt < 4; ++mt)
                    #pragma unroll
                    for (int nt = 0; nt < 4; ++nt)
                        #pragma unroll
                        for (int i = 0; i < 4; ++i) sacc[mt][nt][i] <<= 7;
            }
        }

        // ---- epilogue: raw (float)acc -> smem [px][65]; bucketize ----
        __syncthreads();
        float* sum = reinterpret_cast<float*>(smem);
        #pragma unroll
        for (int mt = 0; mt < 4; ++mt)
            #pragma unroll
            for (int nt = 0; nt < 4; ++nt)
                #pragma unroll
                for (int i = 0; i < 4; ++i) {
                    const int row = wm * 64 + mt * 16 + (lane >> 2) + ((i >> 1) << 3);
                    const int col = wn * 32 + nt * 8 + ((lane & 3) << 1) + (i & 1);
                    sum[row * 65 + col] = (float)sacc[mt][nt][i];
                }
        __syncthreads();

        const int j = tid;               // pixel 0..127
        const int s = s0 + j;
        const int rimg = s / 114 - 1;
        const int c = s - (rimg + 1) * 114;
        if (c < 112 && rimg < 112) {
            const int q = rimg * 112 + c;
            float* op = out + (size_t)n * 64 * 12544 + q;
            const float* sl = reinterpret_cast<const float*>(smem + LUT_OFF);
            #pragma unroll 4
            for (int co = 0; co < 64; ++co) {
                const float v = sum[j * 65 + co];
                const float* tt = sl + co * 7;
                float r = 0.f;
                if (v >  tt[0]) r = 1.f;
                if (v >= tt[1]) r = 2.f;
                if (v >  tt[2]) r = 3.f;
                if (v >= tt[3]) r = 4.f;
                if (v >  tt[4]) r = 5.f;
                if (v >= tt[5]) r = 6.f;
                if (v >  tt[6]) r = 7.f;
                op[(size_t)co * 12544] = r;
            }
        }
        __syncthreads();   // sum buffer aliases A region: drain before restaging
    }
}

// ---------------------------------------------------------------------------
extern "C" void kernel_launch(void* const* d_in, const int* in_sizes, int n_in,
                              void* d_out, int out_size) {
    (void)in_sizes; (void)n_in; (void)out_size;
    const float* x   = (const float*)d_in[0];
    const float* w   = (const float*)d_in[1];
    const float* lut = (const float*)d_in[2];
    float* out = (float*)d_out;

    cudaFuncSetAttribute(conv_mma_kernel,
                         cudaFuncAttributeMaxDynamicSharedMemorySize, SMEM_TOTAL);

    prepass_kernel<<<PRE_BLKS, 256>>>(x, w);
    conv_mma_kernel<<<NCTAS, 128, SMEM_TOTAL>>>(lut, out);
}